// round 7
// baseline (speedup 1.0000x reference)
#include <cuda_runtime.h>
#include <math.h>

// ---------------------------------------------------------------------------
// GCN(2)->node0->LSTM->FC. Only the 2-hop in-neighborhood of node 0 matters:
// S1 = in-neighbors of 0 (~32), S2 = in-neighbors of S1 (~1100).
// Six kernels:
//   1 init   : incremental reset of prev-run entries (1 block), seed node 0
//   2 scan1  : dst==0            -> e0 list, S1 set, bm1
//   3 scan2  : dst in bm1 (SMEM) -> e1 list, S2 set, bm2
//   4 scan3h : dst in bm2 (SMEM) -> deg  ; then hlin = x[:,u]@W1, u in S2
//   5 agg    : layer-1 aggregation into acc1 (self loops + e1, atomics)
//   6 tail   : one block: h2 = relu(acc1+b1)@W2 ; node-0 layer-2 agg ;
//              LSTM single step ; FC -> out
// Scans run at full occupancy (4 CTAs/SM x 512 thr) with 3-deep load batches.
// ---------------------------------------------------------------------------

#define NN_MAX   100000
#define IND      128
#define H        64
#define S1CAP    512
#define E0CAP    2048
#define ECAP     32768
#define BMW      ((NN_MAX + 31) / 32)   // 3125 words = 12.5 KB
#define SCAN_B   592
#define SCAN_T   512
#define NTH      (SCAN_B * SCAN_T)

static __device__ int      g_deg[NN_MAX];
static __device__ int      g_flag1[NN_MAX];   // pos+1 in S1 (0 = not member)
static __device__ int      g_flag2[NN_MAX];   // pos+1 in S2
static __device__ unsigned g_bm1[BMW];
static __device__ unsigned g_bm2[BMW];
static __device__ int      g_s1[S1CAP];
static __device__ int      g_e0[E0CAP];       // src of edges with dst==0
static __device__ int      g_s2[ECAP];
static __device__ int2     g_e1[ECAP];        // edges with dst in S1
static __device__ int      g_cnt1, g_cnt2, g_cntE0, g_cntE1;
static __device__ float    g_hlin[ECAP][H];
static __device__ float    g_acc1[S1CAP][H];
static __device__ float    g_h2[S1CAP][H];

// ---------------------------------------------------------------------------
// Incremental init: reset exactly the entries the previous run touched
// (persisted in g_s1/g_s2 + counters), then seed node 0. First call after
// module load sees counters==0 (static zero-init) -> loops no-op, seed only.
// Every call leaves the identical canonical seeded state -> deterministic.
__global__ void k_init(void) {
    int tid = threadIdx.x;
    int m1 = g_cnt1; if (m1 > S1CAP) m1 = S1CAP;
    int m2 = g_cnt2; if (m2 > ECAP)  m2 = ECAP;
    // entries j>=1 (j==0 is always node 0, re-seeded below)
    for (int j = 1 + tid; j < m1; j += 512) {
        int u = g_s1[j];
        g_flag1[u] = 0;
        atomicAnd(&g_bm1[u >> 5], ~(1u << (u & 31)));
    }
    for (int j = 1 + tid; j < m2; j += 512) {
        int u = g_s2[j];
        g_flag2[u] = 0;
        g_deg[u]   = 0;
        atomicAnd(&g_bm2[u >> 5], ~(1u << (u & 31)));
    }
    for (int k = tid; k < m1 * H; k += 512) ((float*)g_acc1)[k] = 0.0f;
    __syncthreads();
    if (tid == 0) {
        g_cnt1 = 1; g_cnt2 = 1; g_cntE0 = 0; g_cntE1 = 0;
        g_s1[0] = 0; g_s2[0] = 0;
        g_flag1[0] = 1; g_flag2[0] = 1;
        g_deg[0] = 0;
        atomicOr(&g_bm1[0], 1u);
        atomicOr(&g_bm2[0], 1u);
    }
}

// ---------------------------------------------------------------------------
__device__ __forceinline__ void s1_one(const int* __restrict__ src, int d, int idx) {
    if (d == 0) {
        int s = __ldcg(&src[idx]);
        int p = atomicAdd(&g_cntE0, 1);
        if (p < E0CAP) g_e0[p] = s;
        if (atomicCAS(&g_flag1[s], 0, -1) == 0) {
            int q = atomicAdd(&g_cnt1, 1);
            if (q < S1CAP) g_s1[q] = s;
            g_flag1[s] = q + 1;
            atomicOr(&g_bm1[s >> 5], 1u << (s & 31));
            if (atomicCAS(&g_flag2[s], 0, -1) == 0) {
                int r = atomicAdd(&g_cnt2, 1);
                if (r < ECAP) g_s2[r] = s;
                g_flag2[s] = r + 1;
                atomicOr(&g_bm2[s >> 5], 1u << (s & 31));
            }
        }
    }
}

__global__ void __launch_bounds__(SCAN_T, 4)
k_scan1(const int* __restrict__ src, const int* __restrict__ dst, int E) {
    int gid = blockIdx.x * SCAN_T + threadIdx.x;
    int E4 = E >> 2;
    const int4* d4 = (const int4*)dst;
    for (int base = 0; base < E4; base += 3 * NTH) {
        int i0 = base + gid, i1 = i0 + NTH, i2 = i0 + 2 * NTH;
        bool b0 = i0 < E4, b1 = i1 < E4, b2 = i2 < E4;
        int4 v0, v1, v2;
        if (b0) v0 = __ldcg(&d4[i0]);
        if (b1) v1 = __ldcg(&d4[i1]);
        if (b2) v2 = __ldcg(&d4[i2]);
        if (b0) { s1_one(src, v0.x, 4*i0); s1_one(src, v0.y, 4*i0+1); s1_one(src, v0.z, 4*i0+2); s1_one(src, v0.w, 4*i0+3); }
        if (b1) { s1_one(src, v1.x, 4*i1); s1_one(src, v1.y, 4*i1+1); s1_one(src, v1.z, 4*i1+2); s1_one(src, v1.w, 4*i1+3); }
        if (b2) { s1_one(src, v2.x, 4*i2); s1_one(src, v2.y, 4*i2+1); s1_one(src, v2.z, 4*i2+2); s1_one(src, v2.w, 4*i2+3); }
    }
    for (int j = (E4 << 2) + gid; j < E; j += NTH) s1_one(src, __ldcg(&dst[j]), j);
}

// ---------------------------------------------------------------------------
__device__ __forceinline__ void s2_one(const unsigned* sbm,
                                       const int* __restrict__ src, int d, int idx) {
    if ((sbm[d >> 5] >> (d & 31)) & 1u) {
        int s = __ldcg(&src[idx]);
        int p = atomicAdd(&g_cntE1, 1);
        if (p < ECAP) g_e1[p] = make_int2(s, d);
        if (atomicCAS(&g_flag2[s], 0, -1) == 0) {
            int r = atomicAdd(&g_cnt2, 1);
            if (r < ECAP) g_s2[r] = s;
            g_flag2[s] = r + 1;
            atomicOr(&g_bm2[s >> 5], 1u << (s & 31));
        }
    }
}

__global__ void __launch_bounds__(SCAN_T, 4)
k_scan2(const int* __restrict__ src, const int* __restrict__ dst, int E) {
    __shared__ unsigned sbm[BMW];
    for (int k = threadIdx.x; k < BMW; k += SCAN_T) sbm[k] = __ldg(&g_bm1[k]);
    __syncthreads();
    int gid = blockIdx.x * SCAN_T + threadIdx.x;
    int E4 = E >> 2;
    const int4* d4 = (const int4*)dst;
    for (int base = 0; base < E4; base += 3 * NTH) {
        int i0 = base + gid, i1 = i0 + NTH, i2 = i0 + 2 * NTH;
        bool b0 = i0 < E4, b1 = i1 < E4, b2 = i2 < E4;
        int4 v0, v1, v2;
        if (b0) v0 = __ldcg(&d4[i0]);
        if (b1) v1 = __ldcg(&d4[i1]);
        if (b2) v2 = __ldcg(&d4[i2]);
        if (b0) { s2_one(sbm, src, v0.x, 4*i0); s2_one(sbm, src, v0.y, 4*i0+1); s2_one(sbm, src, v0.z, 4*i0+2); s2_one(sbm, src, v0.w, 4*i0+3); }
        if (b1) { s2_one(sbm, src, v1.x, 4*i1); s2_one(sbm, src, v1.y, 4*i1+1); s2_one(sbm, src, v1.z, 4*i1+2); s2_one(sbm, src, v1.w, 4*i1+3); }
        if (b2) { s2_one(sbm, src, v2.x, 4*i2); s2_one(sbm, src, v2.y, 4*i2+1); s2_one(sbm, src, v2.z, 4*i2+2); s2_one(sbm, src, v2.w, 4*i2+3); }
    }
    for (int j = (E4 << 2) + gid; j < E; j += NTH) {
        int d = __ldcg(&dst[j]);
        s2_one(sbm, src, d, j);
    }
}

// ---------------------------------------------------------------------------
// Degree scan (bm2-gated) + hlin = x[:,u] @ W1 for u in S2. Independent work
// (both depend only on scan2 results) -> fused, no internal grid sync needed.
__global__ void __launch_bounds__(SCAN_T, 4)
k_scan3_hlin(const int* __restrict__ dst, int E,
             const float* __restrict__ x, const float* __restrict__ W1, int N) {
    __shared__ unsigned sbm[BMW];       // 12.5 KB
    __shared__ float    sW1[IND * H];   // 32 KB
    __shared__ float    sx[4][IND];     // 2 KB
    for (int k = threadIdx.x; k < BMW; k += SCAN_T) sbm[k] = __ldg(&g_bm2[k]);
    for (int k = threadIdx.x; k < IND * H; k += SCAN_T) sW1[k] = W1[k];
    __syncthreads();

    int gid = blockIdx.x * SCAN_T + threadIdx.x;
    int E4 = E >> 2;
    const int4* d4 = (const int4*)dst;
    #define S3(dd) if ((sbm[(dd) >> 5] >> ((dd) & 31)) & 1u) atomicAdd(&g_deg[dd], 1)
    for (int base = 0; base < E4; base += 3 * NTH) {
        int i0 = base + gid, i1 = i0 + NTH, i2 = i0 + 2 * NTH;
        bool b0 = i0 < E4, b1 = i1 < E4, b2 = i2 < E4;
        int4 v0, v1, v2;
        if (b0) v0 = __ldcg(&d4[i0]);
        if (b1) v1 = __ldcg(&d4[i1]);
        if (b2) v2 = __ldcg(&d4[i2]);
        if (b0) { S3(v0.x); S3(v0.y); S3(v0.z); S3(v0.w); }
        if (b1) { S3(v1.x); S3(v1.y); S3(v1.z); S3(v1.w); }
        if (b2) { S3(v2.x); S3(v2.y); S3(v2.z); S3(v2.w); }
    }
    for (int j = (E4 << 2) + gid; j < E; j += NTH) { int dd = __ldcg(&dst[j]); S3(dd); }
    #undef S3

    // hlin part: 4 nodes per block concurrently (128 threads each stage one
    // x-column in parallel; 64 of them then do the smem dot product).
    __syncthreads();
    int m2 = g_cnt2; if (m2 > ECAP) m2 = ECAP;
    int g  = threadIdx.x >> 7;
    int lt = threadIdx.x & 127;
    for (int base = blockIdx.x * 4; base < m2; base += SCAN_B * 4) {
        int j = base + g;
        int u = (j < m2) ? g_s2[j] : -1;
        if (u >= 0) sx[g][lt] = __ldg(&x[(size_t)lt * N + u]);
        __syncthreads();
        if (u >= 0 && lt < H) {
            float acc = 0.0f;
            #pragma unroll
            for (int d = 0; d < IND; d++) acc += sx[g][d] * sW1[d * H + lt];
            g_hlin[j][lt] = acc;
        }
        __syncthreads();
    }
}

// ---------------------------------------------------------------------------
// Layer-1 aggregation: self loops for S1 nodes + e1 edge scatter.
__global__ void k_agg(void) {
    int sub = threadIdx.x >> 6;          // 4 groups of 64 per block
    int tt  = threadIdx.x & 63;
    int ng  = gridDim.x * 4;
    int gi  = blockIdx.x * 4 + sub;
    int m1 = g_cnt1; if (m1 > S1CAP) m1 = S1CAP;
    for (int j = gi; j < m1; j += ng) {
        int u  = g_s1[j];
        float di = rsqrtf((float)g_deg[u] + 1.0f);
        int p2 = g_flag2[u] - 1;
        atomicAdd(&g_acc1[j][tt], di * di * g_hlin[p2][tt]);
    }
    int mE = g_cntE1; if (mE > ECAP) mE = ECAP;
    for (int e = gi; e < mE; e += ng) {
        int2 ed = g_e1[e];
        int dp = g_flag1[ed.y] - 1;
        int sp = g_flag2[ed.x] - 1;
        float nrm = rsqrtf((float)g_deg[ed.x] + 1.0f) * rsqrtf((float)g_deg[ed.y] + 1.0f);
        atomicAdd(&g_acc1[dp][tt], nrm * g_hlin[sp][tt]);
    }
}

// ---------------------------------------------------------------------------
// Single block: h2 for all S1 nodes, node-0 layer-2 aggregation, LSTM, FC.
__global__ void __launch_bounds__(512)
k_tail(const float* __restrict__ b1, const float* __restrict__ W2,
       const float* __restrict__ b2, const float* __restrict__ w_ih,
       const float* __restrict__ b_ih, const float* __restrict__ b_hh,
       const float* __restrict__ fc_w, const float* __restrict__ fc_b,
       float* __restrict__ out) {
    __shared__ float sW2[H * H];        // 16 KB
    __shared__ float h1buf[8][H];       // 2 KB
    __shared__ float z[H], gates[4 * H], red[H];
    __shared__ float scof[256];
    __shared__ int   sspb[256];

    int tid = threadIdx.x;
    for (int k = tid; k < H * H; k += 512) sW2[k] = W2[k];
    __syncthreads();

    int m1 = g_cnt1; if (m1 > S1CAP) m1 = S1CAP;
    int sub = tid >> 6, tt = tid & 63;
    for (int j0 = 0; j0 < m1; j0 += 8) {
        int j = j0 + sub;
        if (j < m1) h1buf[sub][tt] = fmaxf(g_acc1[j][tt] + b1[tt], 0.0f);
        __syncthreads();
        if (j < m1) {
            float acc = 0.0f;
            #pragma unroll
            for (int h = 0; h < H; h++) acc += h1buf[sub][h] * sW2[h * H + tt];
            g_h2[j][tt] = acc;
        }
        __syncthreads();
    }

    // node-0 layer-2 aggregation
    int m0 = g_cntE0; if (m0 > E0CAP) m0 = E0CAP;
    float d0 = rsqrtf((float)g_deg[0] + 1.0f);
    float zv = 0.0f;
    if (tid < H) zv = b2[tid] + d0 * d0 * g_h2[0][tid];
    for (int base = 0; base < m0; base += 256) {
        int k = base + tid;
        if (tid < 256 && k < m0) {
            int s = g_e0[k];
            scof[tid] = rsqrtf((float)g_deg[s] + 1.0f) * d0;
            sspb[tid] = g_flag1[s] - 1;
        }
        __syncthreads();
        int lim = m0 - base; if (lim > 256) lim = 256;
        if (tid < H)
            for (int e = 0; e < lim; e++) zv += scof[e] * g_h2[sspb[e]][tid];
        __syncthreads();
    }
    if (tid < H) z[tid] = zv;
    __syncthreads();

    if (tid < 4 * H) {
        float a = b_ih[tid] + b_hh[tid];
        #pragma unroll
        for (int h = 0; h < H; h++) a += __ldg(&w_ih[tid * H + h]) * z[h];
        gates[tid] = a;
    }
    __syncthreads();
    if (tid < H) {
        float ig = gates[tid];
        float gg = gates[2 * H + tid];
        float og = gates[3 * H + tid];
        float si = 1.0f / (1.0f + expf(-ig));
        float c  = si * tanhf(gg);
        float so = 1.0f / (1.0f + expf(-og));
        float hy = so * tanhf(c);
        red[tid] = hy * fc_w[tid];
    }
    __syncthreads();
    if (tid == 0) {
        float s = 0.0f;
        for (int k = 0; k < H; k++) s += red[k];
        out[0] = s + fc_b[0];
    }
}

// ---------------------------------------------------------------------------
extern "C" void kernel_launch(void* const* d_in, const int* in_sizes, int n_in,
                              void* d_out, int out_size) {
    const float* x    = (const float*)d_in[0];
    const int*   ei   = (const int*)d_in[1];
    const float* W1   = (const float*)d_in[2];
    const float* b1   = (const float*)d_in[3];
    const float* W2   = (const float*)d_in[4];
    const float* b2   = (const float*)d_in[5];
    const float* w_ih = (const float*)d_in[6];
    // d_in[7] = w_hh (unused: h0 = c0 = 0)
    const float* b_ih = (const float*)d_in[8];
    const float* b_hh = (const float*)d_in[9];
    const float* fc_w = (const float*)d_in[10];
    const float* fc_b = (const float*)d_in[11];
    float* out = (float*)d_out;

    int N = in_sizes[0] / IND;
    int E = in_sizes[1] / 2;
    const int* src = ei;
    const int* dst = ei + E;

    k_init<<<1, 512>>>();
    k_scan1<<<SCAN_B, SCAN_T>>>(src, dst, E);
    k_scan2<<<SCAN_B, SCAN_T>>>(src, dst, E);
    k_scan3_hlin<<<SCAN_B, SCAN_T>>>(dst, E, x, W1, N);
    k_agg<<<148, 256>>>();
    k_tail<<<1, 512>>>(b1, W2, b2, w_ih, b_ih, b_hh, fc_w, fc_b, out);
}